// round 2
// baseline (speedup 1.0000x reference)
#include <cuda_runtime.h>
#include <cstdint>

#define BATCH 4
#define C_DIM 128
#define H_BIG 256
#define W_BIG 256
#define HW_BIG (H_BIG * W_BIG)      // 65536
#define H_SM 128
#define W_SM 128
#define HW_SM (H_SM * W_SM)         // 16384
#define K_NBR 16

// Pixel-major scratch copies (bss, not allocated at runtime)
__device__ float g_ST[(size_t)BATCH * HW_BIG * C_DIM];   // 134 MB
__device__ float g_RT[(size_t)BATCH * HW_BIG * C_DIM];   // 134 MB
__device__ float g_QT[(size_t)BATCH * HW_SM * C_DIM];    //  33 MB

// ---------------------------------------------------------------------------
// Batched transpose: in[b][c][x] (c=0..127, x=0..N-1)  ->  out[b][x][c]
// block (32,8), grid (N/32, 128/32, B)
// ---------------------------------------------------------------------------
__global__ void transpose_kernel(const float* __restrict__ in,
                                 float* __restrict__ out, int N)
{
    __shared__ float tile[32][33];
    const size_t bo = (size_t)blockIdx.z * C_DIM * N;
    const int x  = blockIdx.x * 32 + threadIdx.x;   // spatial (input col)
    const int y0 = blockIdx.y * 32;                 // channel base

    #pragma unroll
    for (int j = threadIdx.y; j < 32; j += 8)
        tile[j][threadIdx.x] = in[bo + (size_t)(y0 + j) * N + x];

    __syncthreads();

    const int oc  = y0 + threadIdx.x;               // output channel
    const int op0 = blockIdx.x * 32;                // output pixel base
    #pragma unroll
    for (int j = threadIdx.y; j < 32; j += 8)
        out[bo + (size_t)(op0 + j) * C_DIM + oc] = tile[threadIdx.x][j];
}

// ---------------------------------------------------------------------------
// Attention kernel: warp-per-pixel, lane holds 4 channels (float4).
// Block = 256 threads = 8 warps = 8 consecutive pixels (same batch).
// ---------------------------------------------------------------------------
__global__ __launch_bounds__(256)
void attn_kernel(const int* __restrict__ Pos,
                 float* __restrict__ outBuf,    // (B, C, hw)
                 float* __restrict__ outM)      // (B, hw, 1, k)
{
    const int warpId = threadIdx.x >> 5;
    const int lane   = threadIdx.x & 31;
    const int gp = blockIdx.x * 8 + warpId;    // global pixel 0..65535
    const int b  = gp >> 14;                   // / 16384
    const int p  = gp & (HW_SM - 1);

    // q for this pixel: 128 contiguous floats, lane takes 4
    const float4 q4 = reinterpret_cast<const float4*>(
        g_QT + (size_t)gp * C_DIM)[lane];

    // lanes 0..15 hold the 16 gather indices for this pixel
    int myidx = 0;
    if (lane < K_NBR) {
        int y = Pos[((size_t)(b * 2 + 0) * HW_SM + p) * K_NBR + lane];
        int x = Pos[((size_t)(b * 2 + 1) * HW_SM + p) * K_NBR + lane];
        myidx = y * W_BIG + x;
    }

    const float* STb = g_ST + (size_t)b * HW_BIG * C_DIM;
    const float* RTb = g_RT + (size_t)b * HW_BIG * C_DIM;

    // ---- scores ----
    float sc[K_NBR];
    #pragma unroll
    for (int j = 0; j < K_NBR; j++) {
        const int idx = __shfl_sync(0xffffffffu, myidx, j);
        const float4 k4 = reinterpret_cast<const float4*>(
            STb + (size_t)idx * C_DIM)[lane];
        float part = q4.x * k4.x + q4.y * k4.y + q4.z * k4.z + q4.w * k4.w;
        part += __shfl_xor_sync(0xffffffffu, part, 16);
        part += __shfl_xor_sync(0xffffffffu, part, 8);
        part += __shfl_xor_sync(0xffffffffu, part, 4);
        part += __shfl_xor_sync(0xffffffffu, part, 2);
        part += __shfl_xor_sync(0xffffffffu, part, 1);
        sc[j] = part;      // identical on all lanes
    }

    // ---- softmax over k=16 (redundant per lane, cheap) ----
    float m = sc[0];
    #pragma unroll
    for (int j = 1; j < K_NBR; j++) m = fmaxf(m, sc[j]);
    float s = 0.f;
    #pragma unroll
    for (int j = 0; j < K_NBR; j++) { sc[j] = __expf(sc[j] - m); s += sc[j]; }
    const float inv = 1.0f / s;
    #pragma unroll
    for (int j = 0; j < K_NBR; j++) sc[j] *= inv;

    // ---- weighted value gather-sum ----
    float4 acc = make_float4(0.f, 0.f, 0.f, 0.f);
    #pragma unroll
    for (int j = 0; j < K_NBR; j++) {
        const int idx = __shfl_sync(0xffffffffu, myidx, j);
        const float4 v4 = reinterpret_cast<const float4*>(
            RTb + (size_t)idx * C_DIM)[lane];
        acc.x += sc[j] * v4.x;
        acc.y += sc[j] * v4.y;
        acc.z += sc[j] * v4.z;
        acc.w += sc[j] * v4.w;
    }

    // ---- attn output: (B, hw, 1, k), contiguous in k ----
    if (lane < K_NBR)
        outM[(size_t)gp * K_NBR + lane] = sc[lane];

    // ---- buffer output: stage in smem, write coalesced per channel ----
    __shared__ float so[8][132];   // pad 132 -> conflict-free on read
    reinterpret_cast<float4*>(&so[warpId][0])[lane] = acc;
    __syncthreads();

    const int bb = (blockIdx.x * 8) >> 14;        // batch for whole block
    const int pb = (blockIdx.x * 8) & (HW_SM - 1);
    const int px = threadIdx.x & 7;
    const int c0 = threadIdx.x >> 3;              // 0..31
    #pragma unroll
    for (int r = 0; r < 4; r++) {
        const int c = c0 + r * 32;
        outBuf[((size_t)bb * C_DIM + c) * HW_SM + pb + px] = so[px][c];
    }
}

extern "C" void kernel_launch(void* const* d_in, const int* in_sizes, int n_in,
                              void* d_out, int out_size)
{
    const float* Q   = (const float*)d_in[0];
    const float* S   = (const float*)d_in[1];
    const float* R   = (const float*)d_in[2];
    const int*   Pos = (const int*)d_in[3];

    float* outBuf = (float*)d_out;                                   // B*C*hw
    float* outM   = outBuf + (size_t)BATCH * C_DIM * HW_SM;          // B*hw*k

    float* dST; cudaGetSymbolAddress((void**)&dST, g_ST);
    float* dRT; cudaGetSymbolAddress((void**)&dRT, g_RT);
    float* dQT; cudaGetSymbolAddress((void**)&dQT, g_QT);

    dim3 tb(32, 8);
    transpose_kernel<<<dim3(HW_BIG / 32, C_DIM / 32, BATCH), tb>>>(S, dST, HW_BIG);
    transpose_kernel<<<dim3(HW_BIG / 32, C_DIM / 32, BATCH), tb>>>(R, dRT, HW_BIG);
    transpose_kernel<<<dim3(HW_SM / 32,  C_DIM / 32, BATCH), tb>>>(Q, dQT, HW_SM);

    attn_kernel<<<(BATCH * HW_SM) / 8, 256>>>(Pos, outBuf, outM);
}

// round 3
// speedup vs baseline: 1.4100x; 1.4100x over previous
#include <cuda_runtime.h>
#include <cstdint>

#define BATCH 4
#define C_DIM 128
#define HW_BIG 65536
#define HW_SM 16384
#define W_BIG 256
#define K_NBR 16

// Single reused per-batch scratch (33.5 MB) — same addresses every phase so
// transpose stores dirty-hit L2 and gather loads stay L2-resident.
__device__ float g_T[(size_t)HW_BIG * C_DIM];

// ---------------------------------------------------------------------------
// One-batch transpose: in[c][p] (C_DIM x HW_BIG) -> out[p][c]
// Tile: 32 pixels x 128 channels, float4 on both global sides,
// smem stride 129 -> conflict-free in both phases (verified lane mapping).
// ---------------------------------------------------------------------------
__global__ __launch_bounds__(256)
void transpose_b(const float* __restrict__ in, float* __restrict__ out)
{
    __shared__ float tile[32][129];
    const int p0 = blockIdx.x * 32;
    const int t  = threadIdx.x;

    #pragma unroll
    for (int i0 = 0; i0 < 4; i0++) {
        const int g  = t + 256 * i0;
        const int c  = g >> 3;            // channel 0..127
        const int pq = (g & 7) * 4;       // pixel quad
        const float4 v = *reinterpret_cast<const float4*>(
            in + (size_t)c * HW_BIG + p0 + pq);
        tile[pq + 0][c] = v.x;
        tile[pq + 1][c] = v.y;
        tile[pq + 2][c] = v.z;
        tile[pq + 3][c] = v.w;
    }
    __syncthreads();

    const int p = t >> 3;                 // pixel 0..31 (4 per warp)
    #pragma unroll
    for (int i0 = 0; i0 < 4; i0++) {
        const int cg = (t & 7) + 8 * i0;  // channel group 0..31
        const float4 v = make_float4(tile[p][4*cg + 0], tile[p][4*cg + 1],
                                     tile[p][4*cg + 2], tile[p][4*cg + 3]);
        *reinterpret_cast<float4*>(out + (size_t)(p0 + p) * C_DIM + 4*cg) = v;
    }
}

// ---------------------------------------------------------------------------
// Score pass: warp-per-pixel; Q staged via smem (fused transpose);
// gathers keys from g_T (L2-resident); softmax over k=16; writes weights.
// ---------------------------------------------------------------------------
__global__ __launch_bounds__(256)
void score_kernel(const float* __restrict__ Q,     // batch base: C x HW_SM
                  const int*   __restrict__ PosY,  // batch base: HW_SM * K
                  const int*   __restrict__ PosX,
                  float*       __restrict__ outM)  // batch base: HW_SM * K
{
    __shared__ float Qs[8][132];
    const int t  = threadIdx.x;
    const int p0 = blockIdx.x * 8;

    // Stage Q[:, p0..p0+7] -> Qs[px][c]; full 32B sectors, conflict-free writes
    #pragma unroll
    for (int i = 0; i < 4; i++) {
        const int c  = (t >> 3) + 32 * i;
        const int px = t & 7;
        Qs[px][c] = Q[(size_t)c * HW_SM + p0 + px];
    }
    __syncthreads();

    const int warpId = t >> 5, lane = t & 31;
    const int p = p0 + warpId;

    const float4 q4 = reinterpret_cast<const float4*>(&Qs[warpId][0])[lane];

    int myidx = 0;
    if (lane < K_NBR) {
        const int y = PosY[p * K_NBR + lane];
        const int x = PosX[p * K_NBR + lane];
        myidx = y * W_BIG + x;
    }

    float sc[K_NBR];
    #pragma unroll
    for (int j = 0; j < K_NBR; j++) {
        const int idx = __shfl_sync(0xffffffffu, myidx, j);
        const float4 k4 = reinterpret_cast<const float4*>(
            g_T + (size_t)idx * C_DIM)[lane];
        float part = q4.x*k4.x + q4.y*k4.y + q4.z*k4.z + q4.w*k4.w;
        part += __shfl_xor_sync(0xffffffffu, part, 16);
        part += __shfl_xor_sync(0xffffffffu, part, 8);
        part += __shfl_xor_sync(0xffffffffu, part, 4);
        part += __shfl_xor_sync(0xffffffffu, part, 2);
        part += __shfl_xor_sync(0xffffffffu, part, 1);
        sc[j] = part;
    }

    float m = sc[0];
    #pragma unroll
    for (int j = 1; j < K_NBR; j++) m = fmaxf(m, sc[j]);
    float s = 0.f;
    #pragma unroll
    for (int j = 0; j < K_NBR; j++) { sc[j] = __expf(sc[j] - m); s += sc[j]; }
    const float inv = 1.0f / s;

    if (lane < K_NBR)
        outM[(size_t)p * K_NBR + lane] = sc[lane] * inv;
}

// ---------------------------------------------------------------------------
// Value pass: warp-per-pixel; gathers values from g_T (L2-resident), weighted
// sum with weights read back from outM; coalesced channel-major output.
// ---------------------------------------------------------------------------
__global__ __launch_bounds__(256)
void value_kernel(const int*   __restrict__ PosY,
                  const int*   __restrict__ PosX,
                  const float* __restrict__ M,      // batch base: HW_SM * K
                  float*       __restrict__ outBuf) // batch base: C x HW_SM
{
    const int t = threadIdx.x, warpId = t >> 5, lane = t & 31;
    const int p0 = blockIdx.x * 8;
    const int p  = p0 + warpId;

    int   myidx = 0;
    float myw   = 0.f;
    if (lane < K_NBR) {
        const int y = PosY[p * K_NBR + lane];
        const int x = PosX[p * K_NBR + lane];
        myidx = y * W_BIG + x;
        myw   = M[(size_t)p * K_NBR + lane];
    }

    float4 acc = make_float4(0.f, 0.f, 0.f, 0.f);
    #pragma unroll
    for (int j = 0; j < K_NBR; j++) {
        const int   idx = __shfl_sync(0xffffffffu, myidx, j);
        const float w   = __shfl_sync(0xffffffffu, myw,   j);
        const float4 v4 = reinterpret_cast<const float4*>(
            g_T + (size_t)idx * C_DIM)[lane];
        acc.x += w * v4.x;
        acc.y += w * v4.y;
        acc.z += w * v4.z;
        acc.w += w * v4.w;
    }

    __shared__ float so[8][132];
    reinterpret_cast<float4*>(&so[warpId][0])[lane] = acc;
    __syncthreads();

    const int px = t & 7;
    const int c0 = t >> 3;
    #pragma unroll
    for (int r = 0; r < 4; r++) {
        const int c = c0 + 32 * r;
        outBuf[(size_t)c * HW_SM + p0 + px] = so[px][c];
    }
}

extern "C" void kernel_launch(void* const* d_in, const int* in_sizes, int n_in,
                              void* d_out, int out_size)
{
    const float* Q   = (const float*)d_in[0];
    const float* S   = (const float*)d_in[1];
    const float* R   = (const float*)d_in[2];
    const int*   Pos = (const int*)d_in[3];

    float* outBuf = (float*)d_out;                                // B*C*hw
    float* outM   = outBuf + (size_t)BATCH * C_DIM * HW_SM;       // B*hw*k

    float* gT; cudaGetSymbolAddress((void**)&gT, g_T);

    for (int b = 0; b < BATCH; b++) {
        const float* Sb = S + (size_t)b * C_DIM * HW_BIG;
        const float* Rb = R + (size_t)b * C_DIM * HW_BIG;
        const float* Qb = Q + (size_t)b * C_DIM * HW_SM;
        const int*   PY = Pos + (size_t)b * 2 * HW_SM * K_NBR;
        const int*   PX = PY + (size_t)HW_SM * K_NBR;
        float*       Mb = outM   + (size_t)b * HW_SM * K_NBR;
        float*       Ob = outBuf + (size_t)b * C_DIM * HW_SM;

        transpose_b <<<HW_BIG / 32, 256>>>(Sb, gT);
        score_kernel<<<HW_SM  /  8, 256>>>(Qb, PY, PX, Mb);
        transpose_b <<<HW_BIG / 32, 256>>>(Rb, gT);
        value_kernel<<<HW_SM  /  8, 256>>>(PY, PX, Mb, Ob);
    }
}

// round 4
// speedup vs baseline: 1.5081x; 1.0696x over previous
#include <cuda_runtime.h>
#include <cstdint>

#define BATCH 4
#define C_DIM 128
#define HW_BIG 65536
#define HW_SM 16384
#define W_BIG 256
#define K_NBR 16

// Two per-batch scratches (33.5 MB each) — both L2-resident (67 MB < 126 MB),
// reused at the same addresses every batch so stores dirty-hit L2.
__device__ float g_TS[(size_t)HW_BIG * C_DIM];
__device__ float g_TR[(size_t)HW_BIG * C_DIM];

// ---------------------------------------------------------------------------
// Fused transpose for S and R (one batch): in[c][p] -> scratch[p][c]
// grid = (2048, 2): y=0 transposes S -> g_TS, y=1 transposes R -> g_TR.
// float4 on both global sides, smem stride 129 (conflict-free both phases).
// ---------------------------------------------------------------------------
__global__ __launch_bounds__(256)
void transpose2_kernel(const float* __restrict__ S, const float* __restrict__ R)
{
    __shared__ float tile[32][129];
    const float* in  = blockIdx.y ? R : S;
    float*       out = blockIdx.y ? g_TR : g_TS;

    const int p0 = blockIdx.x * 32;
    const int t  = threadIdx.x;

    #pragma unroll
    for (int i0 = 0; i0 < 4; i0++) {
        const int g  = t + 256 * i0;
        const int c  = g >> 3;            // channel 0..127
        const int pq = (g & 7) * 4;       // pixel quad
        const float4 v = __ldcs(reinterpret_cast<const float4*>(
            in + (size_t)c * HW_BIG + p0 + pq));
        tile[pq + 0][c] = v.x;
        tile[pq + 1][c] = v.y;
        tile[pq + 2][c] = v.z;
        tile[pq + 3][c] = v.w;
    }
    __syncthreads();

    const int p = t >> 3;                 // pixel 0..31
    #pragma unroll
    for (int i0 = 0; i0 < 4; i0++) {
        const int cg = (t & 7) + 8 * i0;  // channel group 0..31
        const float4 v = make_float4(tile[p][4*cg + 0], tile[p][4*cg + 1],
                                     tile[p][4*cg + 2], tile[p][4*cg + 3]);
        *reinterpret_cast<float4*>(out + (size_t)(p0 + p) * C_DIM + 4*cg) = v;
    }
}

// ---------------------------------------------------------------------------
// Fused attention: score gather + softmax + value gather, warp-per-pixel.
// All 16 indices computed up-front from broadcast int4 loads; gathers issued
// in groups of 8 for high MLP; butterfly reductions pipelined across all 16.
// ---------------------------------------------------------------------------
__global__ __launch_bounds__(256)
void attn_fused_kernel(const float* __restrict__ Q,     // batch: C x HW_SM
                       const int*   __restrict__ PosY,  // batch: HW_SM * K
                       const int*   __restrict__ PosX,
                       float*       __restrict__ outM,  // batch: HW_SM * K
                       float*       __restrict__ outBuf)// batch: C x HW_SM
{
    __shared__ float stage[8][132];
    const int t  = threadIdx.x;
    const int p0 = blockIdx.x * 8;

    // Stage Q[:, p0..p0+7] -> stage[px][c] (full 32B sectors, streaming)
    #pragma unroll
    for (int i = 0; i < 4; i++) {
        const int c  = (t >> 3) + 32 * i;
        const int px = t & 7;
        stage[px][c] = __ldcs(Q + (size_t)c * HW_SM + p0 + px);
    }
    __syncthreads();

    const int warpId = t >> 5, lane = t & 31;
    const int p = p0 + warpId;

    const float4 q4 = reinterpret_cast<const float4*>(&stage[warpId][0])[lane];
    __syncthreads();   // stage[] reused for output below

    // All lanes compute all 16 indices (uniform loads -> warp broadcast)
    int idx[K_NBR];
    {
        const int4* py4 = reinterpret_cast<const int4*>(PosY + (size_t)p * K_NBR);
        const int4* px4 = reinterpret_cast<const int4*>(PosX + (size_t)p * K_NBR);
        #pragma unroll
        for (int i = 0; i < 4; i++) {
            const int4 y = py4[i];
            const int4 x = px4[i];
            idx[4*i + 0] = y.x * W_BIG + x.x;
            idx[4*i + 1] = y.y * W_BIG + x.y;
            idx[4*i + 2] = y.z * W_BIG + x.z;
            idx[4*i + 3] = y.w * W_BIG + x.w;
        }
    }

    // ---- score gathers: two groups of 8 loads in flight ----
    float sc[K_NBR];
    #pragma unroll
    for (int g = 0; g < 2; g++) {
        float4 kv[8];
        #pragma unroll
        for (int j = 0; j < 8; j++)
            kv[j] = reinterpret_cast<const float4*>(
                g_TS + (size_t)idx[g*8 + j] * C_DIM)[lane];
        #pragma unroll
        for (int j = 0; j < 8; j++)
            sc[g*8 + j] = q4.x*kv[j].x + q4.y*kv[j].y
                        + q4.z*kv[j].z + q4.w*kv[j].w;
    }

    // Pipelined butterfly reduction for all 16 scores
    #pragma unroll
    for (int st = 16; st >= 1; st >>= 1) {
        #pragma unroll
        for (int j = 0; j < K_NBR; j++)
            sc[j] += __shfl_xor_sync(0xffffffffu, sc[j], st);
    }

    // ---- softmax (all lanes hold all 16 scores) ----
    float m = sc[0];
    #pragma unroll
    for (int j = 1; j < K_NBR; j++) m = fmaxf(m, sc[j]);
    float s = 0.f;
    #pragma unroll
    for (int j = 0; j < K_NBR; j++) { sc[j] = __expf(sc[j] - m); s += sc[j]; }
    const float inv = 1.0f / s;
    #pragma unroll
    for (int j = 0; j < K_NBR; j++) sc[j] *= inv;

    // M output: (hw, 1, k) contiguous in k, write-once
    if (lane < K_NBR)
        __stcs(outM + (size_t)p * K_NBR + lane, sc[lane]);

    // ---- value gathers: two groups of 8 loads in flight ----
    float4 acc = make_float4(0.f, 0.f, 0.f, 0.f);
    #pragma unroll
    for (int g = 0; g < 2; g++) {
        float4 kv[8];
        #pragma unroll
        for (int j = 0; j < 8; j++)
            kv[j] = reinterpret_cast<const float4*>(
                g_TR + (size_t)idx[g*8 + j] * C_DIM)[lane];
        #pragma unroll
        for (int j = 0; j < 8; j++) {
            const float w = sc[g*8 + j];
            acc.x += w * kv[j].x;
            acc.y += w * kv[j].y;
            acc.z += w * kv[j].z;
            acc.w += w * kv[j].w;
        }
    }

    // ---- buffer output: stage in smem, coalesced channel-major store ----
    reinterpret_cast<float4*>(&stage[warpId][0])[lane] = acc;
    __syncthreads();

    const int px = t & 7;
    const int c0 = t >> 3;
    #pragma unroll
    for (int r = 0; r < 4; r++) {
        const int c = c0 + 32 * r;
        __stcs(outBuf + (size_t)c * HW_SM + p0 + px, stage[px][c]);
    }
}

extern "C" void kernel_launch(void* const* d_in, const int* in_sizes, int n_in,
                              void* d_out, int out_size)
{
    const float* Q   = (const float*)d_in[0];
    const float* S   = (const float*)d_in[1];
    const float* R   = (const float*)d_in[2];
    const int*   Pos = (const int*)d_in[3];

    float* outBuf = (float*)d_out;                                // B*C*hw
    float* outM   = outBuf + (size_t)BATCH * C_DIM * HW_SM;       // B*hw*k

    for (int b = 0; b < BATCH; b++) {
        const float* Sb = S + (size_t)b * C_DIM * HW_BIG;
        const float* Rb = R + (size_t)b * C_DIM * HW_BIG;
        const float* Qb = Q + (size_t)b * C_DIM * HW_SM;
        const int*   PY = Pos + (size_t)b * 2 * HW_SM * K_NBR;
        const int*   PX = PY + (size_t)HW_SM * K_NBR;
        float*       Mb = outM   + (size_t)b * HW_SM * K_NBR;
        float*       Ob = outBuf + (size_t)b * C_DIM * HW_SM;

        transpose2_kernel<<<dim3(HW_BIG / 32, 2), 256>>>(Sb, Rb);
        attn_fused_kernel<<<HW_SM / 8, 256>>>(Qb, PY, PX, Mb, Ob);
    }
}